// round 1
// baseline (speedup 1.0000x reference)
#include <cuda_runtime.h>
#include <cuda_bf16.h>
#include <math.h>

#define NSTATE 64
#define SEQLEN 8192
#define NBATCH 2048
#define TCHUNK 128
#define NCHUNK 64   // SEQLEN / TCHUNK

// ---------------- device scratch (static, no allocs) ----------------
__device__ float g_Pt[NSTATE * TCHUNK];          // Pt[k][r] = (C Ab^r)[k]
__device__ float g_Vt[NSTATE * TCHUNK];          // Vt[n][j] = (Ab^{T-j} Bb)[n]
__device__ float g_K [TCHUNK];                   // K[l] = C Ab^l Bb
__device__ float g_W [NSTATE * NSTATE];          // W = Ab^T
__device__ float g_X [(size_t)NBATCH * NCHUNK * NSTATE]; // chunk-start states (32MB)
__device__ float g_G [(size_t)NBATCH * NCHUNK * NSTATE]; // chunk input projections (32MB)

// ---------------- kernel A: setup (1 block, 256 threads) ----------------
// dynamic smem: s0[64*65], s1[64*65], s2[64*65], prev[64], cur[64], bb[64], colp[64]
__global__ void __launch_bounds__(256) ssm_setup(
    const float* __restrict__ A, const float* __restrict__ Bv,
    const float* __restrict__ Cv, const float* __restrict__ logstep)
{
    extern __shared__ float sm[];
    float* s0   = sm;                 // 4160
    float* s1   = sm + 4160;          // 4160
    float* s2   = sm + 8320;          // 4160  (holds Ab, padded stride 65)
    float* prev = sm + 12480;
    float* cur  = prev + 64;
    float* bb   = cur + 64;
    float* colp = bb + 64;

    const int t = threadIdx.x;
    const float s = expf(logstep[0]);
    const float h = 0.5f * s;

    // M = I - h*A  -> s0 ; Inv = I -> s1  (both padded stride 65)
    for (int idx = t; idx < 4096; idx += 256) {
        int i = idx >> 6, j = idx & 63;
        float a = A[idx];
        s0[i * 65 + j] = (i == j ? 1.0f : 0.0f) - h * a;
        s1[i * 65 + j] = (i == j ? 1.0f : 0.0f);
    }
    __syncthreads();

    // Gauss-Jordan (no pivoting: matrix ~ I, extremely well conditioned)
    for (int p = 0; p < 64; p++) {
        if (t < 64) colp[t] = s0[t * 65 + p];
        __syncthreads();
        float pivinv = 1.0f / colp[p];
        if (t < 128) {
            if (t < 64) s0[p * 65 + t] *= pivinv;
            else        s1[p * 65 + (t - 64)] *= pivinv;
        }
        __syncthreads();
        for (int idx = t; idx < 64 * 128; idx += 256) {
            int i = idx >> 7, j = idx & 127;
            if (i != p) {
                float f = colp[i] * pivinv;
                if (j < 64) s0[i * 65 + j] -= f * s0[p * 65 + j];
                else        s1[i * 65 + (j - 64)] -= f * s1[p * 65 + (j - 64)];
            }
        }
        __syncthreads();
    }
    // s1 = Minv.  Ab = Minv + h * Minv @ A  -> s2 (padded)
    for (int idx = t; idx < 4096; idx += 256) {
        int i = idx >> 6, j = idx & 63;
        float acc = 0.0f;
        for (int k = 0; k < 64; k++) acc += s1[i * 65 + k] * A[k * 64 + j];
        s2[i * 65 + j] = s1[i * 65 + j] + h * acc;
    }
    __syncthreads();
    // Bb = s * Minv @ B
    if (t < 64) {
        float acc = 0.0f;
        for (int k = 0; k < 64; k++) acc += s1[t * 65 + k] * Bv[k];
        bb[t] = s * acc;
    }
    __syncthreads();

    // P rows: P[0] = C; P[r] = P[r-1] @ Ab. Store transposed: g_Pt[k*128 + r]
    if (t < 64) { prev[t] = Cv[t]; g_Pt[t * TCHUNK + 0] = prev[t]; }
    __syncthreads();
    for (int r = 1; r < TCHUNK; r++) {
        if (t < 64) {
            float acc = 0.0f;
            for (int k = 0; k < 64; k++) acc += prev[k] * s2[k * 65 + t];
            cur[t] = acc;
        }
        __syncthreads();
        if (t < 64) { prev[t] = cur[t]; g_Pt[t * TCHUNK + r] = cur[t]; }
        __syncthreads();
    }
    // K[l] = P[l] . Bb  (Pt is complete + syncthreads orders global within block)
    if (t < TCHUNK) {
        float acc = 0.0f;
        for (int n = 0; n < 64; n++) acc += g_Pt[n * TCHUNK + t] * bb[n];
        g_K[t] = acc;
    }
    __syncthreads();

    // V: V[T-1] = Ab @ Bb ; V[j] = Ab @ V[j+1]. Store transposed g_Vt[n*128 + j]
    if (t < 64) {
        float acc = 0.0f;
        for (int k = 0; k < 64; k++) acc += s2[t * 65 + k] * bb[k];
        prev[t] = acc;
        g_Vt[t * TCHUNK + (TCHUNK - 1)] = acc;
    }
    __syncthreads();
    for (int j = TCHUNK - 2; j >= 0; j--) {
        if (t < 64) {
            float acc = 0.0f;
            for (int k = 0; k < 64; k++) acc += s2[t * 65 + k] * prev[k];
            cur[t] = acc;
        }
        __syncthreads();
        if (t < 64) { prev[t] = cur[t]; g_Vt[t * TCHUNK + j] = cur[t]; }
        __syncthreads();
    }

    // W = Ab^128 via 7 squarings (ping-pong s0 <-> s1)
    for (int idx = t; idx < 4096; idx += 256) {
        int i = idx >> 6, j = idx & 63;
        s0[i * 65 + j] = s2[i * 65 + j];
    }
    __syncthreads();
    float* src = s0; float* dst = s1;
    for (int it = 0; it < 7; it++) {
        for (int idx = t; idx < 4096; idx += 256) {
            int i = idx >> 6, j = idx & 63;
            float acc = 0.0f;
            #pragma unroll 8
            for (int k = 0; k < 64; k++) acc += src[i * 65 + k] * src[k * 65 + j];
            dst[i * 65 + j] = acc;
        }
        __syncthreads();
        float* tmp = src; src = dst; dst = tmp;
    }
    // result ended in src after the final swap
    for (int idx = t; idx < 4096; idx += 256) {
        int i = idx >> 6, j = idx & 63;
        g_W[idx] = src[i * 65 + j];
    }
}

// ---------------- kernel B: G[b][c][n] = sum_j Vt[n][j] * u[b][c*128+j] ----
__global__ void __launch_bounds__(256) ssm_gproj(const float* __restrict__ u)
{
    __shared__ __align__(16) float Vt_s[64 * 132];  // rows padded to 132
    __shared__ __align__(16) float u_s[16 * 128];
    const int c = blockIdx.x, bt = blockIdx.y, tid = threadIdx.x;

    for (int idx = tid; idx < 64 * 128; idx += 256) {
        int n = idx >> 7, j = idx & 127;
        Vt_s[n * 132 + j] = g_Vt[idx];
    }
    const float* ubase = u + (size_t)bt * 16 * SEQLEN + (size_t)c * TCHUNK;
    for (int idx = tid; idx < 512; idx += 256) {
        int b = idx >> 5, q = idx & 31;
        ((float4*)u_s)[b * 32 + q] =
            ((const float4*)(ubase + (size_t)b * SEQLEN))[q];
    }
    __syncthreads();

    const int w = tid >> 5, rg = tid & 31;
    const int bA = w, bB = w + 8;
    float a00 = 0.f, a01 = 0.f, a10 = 0.f, a11 = 0.f;
    const float4* uA4 = (const float4*)(u_s + bA * 128);
    const float4* uB4 = (const float4*)(u_s + bB * 128);
    const float4* v04 = (const float4*)(Vt_s + rg * 132);
    const float4* v14 = (const float4*)(Vt_s + (rg + 32) * 132);
    #pragma unroll 8
    for (int q = 0; q < 32; q++) {
        float4 ua = uA4[q], ub = uB4[q];
        float4 v0 = v04[q], v1 = v14[q];
        a00 += v0.x * ua.x + v0.y * ua.y + v0.z * ua.z + v0.w * ua.w;
        a01 += v1.x * ua.x + v1.y * ua.y + v1.z * ua.z + v1.w * ua.w;
        a10 += v0.x * ub.x + v0.y * ub.y + v0.z * ub.z + v0.w * ub.w;
        a11 += v1.x * ub.x + v1.y * ub.y + v1.z * ub.z + v1.w * ub.w;
    }
    const size_t gA = ((size_t)(bt * 16 + bA) * NCHUNK + c) * NSTATE;
    const size_t gB = ((size_t)(bt * 16 + bB) * NCHUNK + c) * NSTATE;
    g_G[gA + rg]      = a00;
    g_G[gA + rg + 32] = a01;
    g_G[gB + rg]      = a10;
    g_G[gB + rg + 32] = a11;
}

// ---------------- kernel C: per-row chunk scan  x_{c+1} = W x_c + G[c] ----
__global__ void __launch_bounds__(64) ssm_scan()
{
    __shared__ __align__(16) float W_s[64 * 65];
    __shared__ __align__(16) float xs[64];
    const int b = blockIdx.x, t = threadIdx.x;

    for (int idx = t; idx < 4096; idx += 64)
        W_s[(idx >> 6) * 65 + (idx & 63)] = g_W[idx];
    __syncthreads();
    float wrow[64];
    #pragma unroll
    for (int k = 0; k < 64; k++) wrow[k] = W_s[t * 65 + k];

    xs[t] = 0.0f;
    float xv = 0.0f;
    __syncthreads();
    const size_t base = (size_t)b * NCHUNK * NSTATE;
    for (int c = 0; c < NCHUNK; c++) {
        g_X[base + (size_t)c * NSTATE + t] = xv;   // state at chunk start
        float acc = g_G[base + (size_t)c * NSTATE + t];
        #pragma unroll
        for (int k0 = 0; k0 < 64; k0 += 4) {
            float4 xq = *(const float4*)(xs + k0);
            acc += wrow[k0] * xq.x;
            acc += wrow[k0 + 1] * xq.y;
            acc += wrow[k0 + 2] * xq.z;
            acc += wrow[k0 + 3] * xq.w;
        }
        __syncthreads();
        xs[t] = acc; xv = acc;
        __syncthreads();
    }
}

// ---------------- kernel D: outputs  y = P.x + triangular conv + D*u ------
__global__ void __launch_bounds__(256) ssm_out(
    const float* __restrict__ u, float* __restrict__ y,
    const float* __restrict__ Dp)
{
    __shared__ __align__(16) float Pt_s[64 * 128];
    __shared__ __align__(16) float u_s[16 * 128];
    __shared__ __align__(16) float X_s[16 * 64];
    __shared__ __align__(16) float Kpad[256];      // Kpad[128+l] = K[l], else 0
    const int c = blockIdx.x, bt = blockIdx.y, tid = threadIdx.x;
    const float Dv = Dp[0];

    for (int idx = tid; idx < 64 * 128; idx += 256) Pt_s[idx] = g_Pt[idx];
    Kpad[tid] = (tid >= 128) ? g_K[tid - 128] : 0.0f;
    const float* ubase = u + (size_t)bt * 16 * SEQLEN + (size_t)c * TCHUNK;
    for (int idx = tid; idx < 512; idx += 256) {
        int b = idx >> 5, q = idx & 31;
        ((float4*)u_s)[b * 32 + q] =
            ((const float4*)(ubase + (size_t)b * SEQLEN))[q];
    }
    for (int idx = tid; idx < 1024; idx += 256) {
        int b = idx >> 6, n = idx & 63;
        X_s[idx] = g_X[((size_t)(bt * 16 + b) * NCHUNK + c) * NSTATE + n];
    }
    __syncthreads();

    const int w = tid >> 5, rg = tid & 31;
    const int bA = w, bB = w + 8;
    float accA[4] = {0.f, 0.f, 0.f, 0.f};
    float accB[4] = {0.f, 0.f, 0.f, 0.f};
    const float4* Kp4 = (const float4*)Kpad;
    const float4* uA4 = (const float4*)(u_s + bA * 128);
    const float4* uB4 = (const float4*)(u_s + bB * 128);

    // causal intra-chunk conv: thread owns outputs r0..r0+3 (r0 = 4*rg),
    // sliding register window over zero-padded K — no predication.
    float4 Kb = Kp4[32 + rg];       // K[d..d+3],   d = r0
    float4 Ka = Kp4[31 + rg];       // K[d-4..d-1]
    #pragma unroll 4
    for (int it = 0; it < 32; it++) {
        float4 ua = uA4[it], ub = uB4[it];
        float k0 = Kb.x, k1 = Kb.y, k2 = Kb.z, k3 = Kb.w;   // off 0..3
        float km1 = Ka.w, km2 = Ka.z, km3 = Ka.y;           // off -1..-3
        accA[0] += k0 * ua.x + km1 * ua.y + km2 * ua.z + km3 * ua.w;
        accA[1] += k1 * ua.x + k0  * ua.y + km1 * ua.z + km2 * ua.w;
        accA[2] += k2 * ua.x + k1  * ua.y + k0  * ua.z + km1 * ua.w;
        accA[3] += k3 * ua.x + k2  * ua.y + k1  * ua.z + k0  * ua.w;
        accB[0] += k0 * ub.x + km1 * ub.y + km2 * ub.z + km3 * ub.w;
        accB[1] += k1 * ub.x + k0  * ub.y + km1 * ub.z + km2 * ub.w;
        accB[2] += k2 * ub.x + k1  * ub.y + k0  * ub.z + km1 * ub.w;
        accB[3] += k3 * ub.x + k2  * ub.y + k1  * ub.z + k0  * ub.w;
        Kb = Ka;
        if (it < 31) Ka = Kp4[30 + rg - it];
    }

    // y += P[r] . x_c   (Pt[k][r], float4 over r)
    const float4* X4A = (const float4*)(X_s + bA * 64);
    const float4* X4B = (const float4*)(X_s + bB * 64);
    #pragma unroll 4
    for (int kq = 0; kq < 16; kq++) {
        float4 xa = X4A[kq], xb = X4B[kq];
        float4 p0 = *(const float4*)(Pt_s + (4 * kq + 0) * 128 + 4 * rg);
        float4 p1 = *(const float4*)(Pt_s + (4 * kq + 1) * 128 + 4 * rg);
        float4 p2 = *(const float4*)(Pt_s + (4 * kq + 2) * 128 + 4 * rg);
        float4 p3 = *(const float4*)(Pt_s + (4 * kq + 3) * 128 + 4 * rg);
        accA[0] += p0.x * xa.x + p1.x * xa.y + p2.x * xa.z + p3.x * xa.w;
        accA[1] += p0.y * xa.x + p1.y * xa.y + p2.y * xa.z + p3.y * xa.w;
        accA[2] += p0.z * xa.x + p1.z * xa.y + p2.z * xa.z + p3.z * xa.w;
        accA[3] += p0.w * xa.x + p1.w * xa.y + p2.w * xa.z + p3.w * xa.w;
        accB[0] += p0.x * xb.x + p1.x * xb.y + p2.x * xb.z + p3.x * xb.w;
        accB[1] += p0.y * xb.x + p1.y * xb.y + p2.y * xb.z + p3.y * xb.w;
        accB[2] += p0.z * xb.x + p1.z * xb.y + p2.z * xb.z + p3.z * xb.w;
        accB[3] += p0.w * xb.x + p1.w * xb.y + p2.w * xb.z + p3.w * xb.w;
    }

    // + D * u  and store
    {
        float4 ua = uA4[rg], ub = uB4[rg];
        accA[0] += Dv * ua.x; accA[1] += Dv * ua.y;
        accA[2] += Dv * ua.z; accA[3] += Dv * ua.w;
        accB[0] += Dv * ub.x; accB[1] += Dv * ub.y;
        accB[2] += Dv * ub.z; accB[3] += Dv * ub.w;
    }
    float* yA = y + (size_t)(bt * 16 + bA) * SEQLEN + (size_t)c * TCHUNK + 4 * rg;
    float* yB = y + (size_t)(bt * 16 + bB) * SEQLEN + (size_t)c * TCHUNK + 4 * rg;
    *(float4*)yA = make_float4(accA[0], accA[1], accA[2], accA[3]);
    *(float4*)yB = make_float4(accB[0], accB[1], accB[2], accB[3]);
}

// ---------------- launch ----------------
extern "C" void kernel_launch(void* const* d_in, const int* in_sizes, int n_in,
                              void* d_out, int out_size)
{
    const float* u  = (const float*)d_in[0];
    const float* A  = (const float*)d_in[1];
    const float* Bv = (const float*)d_in[2];
    const float* Cv = (const float*)d_in[3];
    const float* Dp = (const float*)d_in[4];
    const float* ls = (const float*)d_in[5];
    float* y = (float*)d_out;

    static const int SMEM_SETUP = 12736 * 4;  // 50944 B
    cudaFuncSetAttribute(ssm_setup, cudaFuncAttributeMaxDynamicSharedMemorySize,
                         SMEM_SETUP);

    ssm_setup<<<1, 256, SMEM_SETUP>>>(A, Bv, Cv, ls);
    ssm_gproj<<<dim3(NCHUNK, NBATCH / 16), 256>>>(u);
    ssm_scan<<<NBATCH, 64>>>();
    ssm_out<<<dim3(NCHUNK, NBATCH / 16), 256>>>(u, y, Dp);
}

// round 2
// speedup vs baseline: 1.0009x; 1.0009x over previous
#include <cuda_runtime.h>
#include <cuda_bf16.h>
#include <math.h>

#define NSTATE 64
#define SEQLEN 8192
#define NBATCH 2048
#define TCHUNK 128
#define NCHUNK 64   // SEQLEN / TCHUNK

// ---------------- device scratch (static, no allocs) ----------------
__device__ float g_Pt[NSTATE * TCHUNK];          // Pt[k][r] = (C Ab^r)[k]
__device__ float g_Vt[NSTATE * TCHUNK];          // Vt[n][j] = (Ab^{T-j} Bb)[n]
__device__ float g_K [TCHUNK];                   // K[l] = C Ab^l Bb
__device__ float g_W [NSTATE * NSTATE];          // W = Ab^T
__device__ float g_X [(size_t)NBATCH * NCHUNK * NSTATE]; // chunk-start states (32MB)
__device__ float g_G [(size_t)NBATCH * NCHUNK * NSTATE]; // chunk input projections (32MB)

// ---------------- kernel A: setup (1 block, 256 threads) ----------------
// dynamic smem: s0[64*65], s1[64*65], s2[64*65], prev[64], cur[64], bb[64], colp[64]
__global__ void __launch_bounds__(256) ssm_setup(
    const float* __restrict__ A, const float* __restrict__ Bv,
    const float* __restrict__ Cv, const float* __restrict__ logstep)
{
    extern __shared__ float sm[];
    float* s0   = sm;                 // 4160
    float* s1   = sm + 4160;          // 4160
    float* s2   = sm + 8320;          // 4160  (holds Ab, padded stride 65)
    float* prev = sm + 12480;
    float* cur  = prev + 64;
    float* bb   = cur + 64;
    float* colp = bb + 64;

    const int t = threadIdx.x;
    const float s = expf(logstep[0]);
    const float h = 0.5f * s;

    // M = I - h*A  -> s0 ; Inv = I -> s1  (both padded stride 65)
    for (int idx = t; idx < 4096; idx += 256) {
        int i = idx >> 6, j = idx & 63;
        float a = A[idx];
        s0[i * 65 + j] = (i == j ? 1.0f : 0.0f) - h * a;
        s1[i * 65 + j] = (i == j ? 1.0f : 0.0f);
    }
    __syncthreads();

    // Gauss-Jordan (no pivoting: matrix ~ I, extremely well conditioned)
    for (int p = 0; p < 64; p++) {
        if (t < 64) colp[t] = s0[t * 65 + p];
        __syncthreads();
        float pivinv = 1.0f / colp[p];
        if (t < 128) {
            if (t < 64) s0[p * 65 + t] *= pivinv;
            else        s1[p * 65 + (t - 64)] *= pivinv;
        }
        __syncthreads();
        for (int idx = t; idx < 64 * 128; idx += 256) {
            int i = idx >> 7, j = idx & 127;
            if (i != p) {
                float f = colp[i] * pivinv;
                if (j < 64) s0[i * 65 + j] -= f * s0[p * 65 + j];
                else        s1[i * 65 + (j - 64)] -= f * s1[p * 65 + (j - 64)];
            }
        }
        __syncthreads();
    }
    // s1 = Minv.  Ab = Minv + h * Minv @ A  -> s2 (padded)
    for (int idx = t; idx < 4096; idx += 256) {
        int i = idx >> 6, j = idx & 63;
        float acc = 0.0f;
        for (int k = 0; k < 64; k++) acc += s1[i * 65 + k] * A[k * 64 + j];
        s2[i * 65 + j] = s1[i * 65 + j] + h * acc;
    }
    __syncthreads();
    // Bb = s * Minv @ B
    if (t < 64) {
        float acc = 0.0f;
        for (int k = 0; k < 64; k++) acc += s1[t * 65 + k] * Bv[k];
        bb[t] = s * acc;
    }
    __syncthreads();

    // P rows: P[0] = C; P[r] = P[r-1] @ Ab. Store transposed: g_Pt[k*128 + r]
    if (t < 64) { prev[t] = Cv[t]; g_Pt[t * TCHUNK + 0] = prev[t]; }
    __syncthreads();
    for (int r = 1; r < TCHUNK; r++) {
        if (t < 64) {
            float acc = 0.0f;
            for (int k = 0; k < 64; k++) acc += prev[k] * s2[k * 65 + t];
            cur[t] = acc;
        }
        __syncthreads();
        if (t < 64) { prev[t] = cur[t]; g_Pt[t * TCHUNK + r] = cur[t]; }
        __syncthreads();
    }
    // K[l] = P[l] . Bb  (Pt is complete + syncthreads orders global within block)
    if (t < TCHUNK) {
        float acc = 0.0f;
        for (int n = 0; n < 64; n++) acc += g_Pt[n * TCHUNK + t] * bb[n];
        g_K[t] = acc;
    }
    __syncthreads();

    // V: V[T-1] = Ab @ Bb ; V[j] = Ab @ V[j+1]. Store transposed g_Vt[n*128 + j]
    if (t < 64) {
        float acc = 0.0f;
        for (int k = 0; k < 64; k++) acc += s2[t * 65 + k] * bb[k];
        prev[t] = acc;
        g_Vt[t * TCHUNK + (TCHUNK - 1)] = acc;
    }
    __syncthreads();
    for (int j = TCHUNK - 2; j >= 0; j--) {
        if (t < 64) {
            float acc = 0.0f;
            for (int k = 0; k < 64; k++) acc += s2[t * 65 + k] * prev[k];
            cur[t] = acc;
        }
        __syncthreads();
        if (t < 64) { prev[t] = cur[t]; g_Vt[t * TCHUNK + j] = cur[t]; }
        __syncthreads();
    }

    // W = Ab^128 via 7 squarings (ping-pong s0 <-> s1)
    for (int idx = t; idx < 4096; idx += 256) {
        int i = idx >> 6, j = idx & 63;
        s0[i * 65 + j] = s2[i * 65 + j];
    }
    __syncthreads();
    float* src = s0; float* dst = s1;
    for (int it = 0; it < 7; it++) {
        for (int idx = t; idx < 4096; idx += 256) {
            int i = idx >> 6, j = idx & 63;
            float acc = 0.0f;
            #pragma unroll 8
            for (int k = 0; k < 64; k++) acc += src[i * 65 + k] * src[k * 65 + j];
            dst[i * 65 + j] = acc;
        }
        __syncthreads();
        float* tmp = src; src = dst; dst = tmp;
    }
    // result ended in src after the final swap
    for (int idx = t; idx < 4096; idx += 256) {
        int i = idx >> 6, j = idx & 63;
        g_W[idx] = src[i * 65 + j];
    }
}

// ---------------- kernel B: G[b][c][n] = sum_j Vt[n][j] * u[b][c*128+j] ----
__global__ void __launch_bounds__(256) ssm_gproj(const float* __restrict__ u)
{
    __shared__ __align__(16) float Vt_s[64 * 132];  // rows padded to 132
    __shared__ __align__(16) float u_s[16 * 128];
    const int c = blockIdx.x, bt = blockIdx.y, tid = threadIdx.x;

    for (int idx = tid; idx < 64 * 128; idx += 256) {
        int n = idx >> 7, j = idx & 127;
        Vt_s[n * 132 + j] = g_Vt[idx];
    }
    const float* ubase = u + (size_t)bt * 16 * SEQLEN + (size_t)c * TCHUNK;
    for (int idx = tid; idx < 512; idx += 256) {
        int b = idx >> 5, q = idx & 31;
        ((float4*)u_s)[b * 32 + q] =
            ((const float4*)(ubase + (size_t)b * SEQLEN))[q];
    }
    __syncthreads();

    const int w = tid >> 5, rg = tid & 31;
    const int bA = w, bB = w + 8;
    float a00 = 0.f, a01 = 0.f, a10 = 0.f, a11 = 0.f;
    const float4* uA4 = (const float4*)(u_s + bA * 128);
    const float4* uB4 = (const float4*)(u_s + bB * 128);
    const float4* v04 = (const float4*)(Vt_s + rg * 132);
    const float4* v14 = (const float4*)(Vt_s + (rg + 32) * 132);
    #pragma unroll 8
    for (int q = 0; q < 32; q++) {
        float4 ua = uA4[q], ub = uB4[q];
        float4 v0 = v04[q], v1 = v14[q];
        a00 += v0.x * ua.x + v0.y * ua.y + v0.z * ua.z + v0.w * ua.w;
        a01 += v1.x * ua.x + v1.y * ua.y + v1.z * ua.z + v1.w * ua.w;
        a10 += v0.x * ub.x + v0.y * ub.y + v0.z * ub.z + v0.w * ub.w;
        a11 += v1.x * ub.x + v1.y * ub.y + v1.z * ub.z + v1.w * ub.w;
    }
    const size_t gA = ((size_t)(bt * 16 + bA) * NCHUNK + c) * NSTATE;
    const size_t gB = ((size_t)(bt * 16 + bB) * NCHUNK + c) * NSTATE;
    g_G[gA + rg]      = a00;
    g_G[gA + rg + 32] = a01;
    g_G[gB + rg]      = a10;
    g_G[gB + rg + 32] = a11;
}

// ---------------- kernel C: per-row chunk scan  x_{c+1} = W x_c + G[c] ----
__global__ void __launch_bounds__(64) ssm_scan()
{
    __shared__ __align__(16) float W_s[64 * 65];
    __shared__ __align__(16) float xs[64];
    const int b = blockIdx.x, t = threadIdx.x;

    for (int idx = t; idx < 4096; idx += 64)
        W_s[(idx >> 6) * 65 + (idx & 63)] = g_W[idx];
    __syncthreads();
    float wrow[64];
    #pragma unroll
    for (int k = 0; k < 64; k++) wrow[k] = W_s[t * 65 + k];

    xs[t] = 0.0f;
    float xv = 0.0f;
    __syncthreads();
    const size_t base = (size_t)b * NCHUNK * NSTATE;
    for (int c = 0; c < NCHUNK; c++) {
        g_X[base + (size_t)c * NSTATE + t] = xv;   // state at chunk start
        float acc = g_G[base + (size_t)c * NSTATE + t];
        #pragma unroll
        for (int k0 = 0; k0 < 64; k0 += 4) {
            float4 xq = *(const float4*)(xs + k0);
            acc += wrow[k0] * xq.x;
            acc += wrow[k0 + 1] * xq.y;
            acc += wrow[k0 + 2] * xq.z;
            acc += wrow[k0 + 3] * xq.w;
        }
        __syncthreads();
        xs[t] = acc; xv = acc;
        __syncthreads();
    }
}

// ---------------- kernel D: outputs  y = P.x + triangular conv + D*u ------
__global__ void __launch_bounds__(256) ssm_out(
    const float* __restrict__ u, float* __restrict__ y,
    const float* __restrict__ Dp)
{
    __shared__ __align__(16) float Pt_s[64 * 128];
    __shared__ __align__(16) float u_s[16 * 128];
    __shared__ __align__(16) float X_s[16 * 64];
    __shared__ __align__(16) float Kpad[256];      // Kpad[128+l] = K[l], else 0
    const int c = blockIdx.x, bt = blockIdx.y, tid = threadIdx.x;
    const float Dv = Dp[0];

    for (int idx = tid; idx < 64 * 128; idx += 256) Pt_s[idx] = g_Pt[idx];
    Kpad[tid] = (tid >= 128) ? g_K[tid - 128] : 0.0f;
    const float* ubase = u + (size_t)bt * 16 * SEQLEN + (size_t)c * TCHUNK;
    for (int idx = tid; idx < 512; idx += 256) {
        int b = idx >> 5, q = idx & 31;
        ((float4*)u_s)[b * 32 + q] =
            ((const float4*)(ubase + (size_t)b * SEQLEN))[q];
    }
    for (int idx = tid; idx < 1024; idx += 256) {
        int b = idx >> 6, n = idx & 63;
        X_s[idx] = g_X[((size_t)(bt * 16 + b) * NCHUNK + c) * NSTATE + n];
    }
    __syncthreads();

    const int w = tid >> 5, rg = tid & 31;
    const int bA = w, bB = w + 8;
    float accA[4] = {0.f, 0.f, 0.f, 0.f};
    float accB[4] = {0.f, 0.f, 0.f, 0.f};
    const float4* Kp4 = (const float4*)Kpad;
    const float4* uA4 = (const float4*)(u_s + bA * 128);
    const float4* uB4 = (const float4*)(u_s + bB * 128);

    // causal intra-chunk conv: thread owns outputs r0..r0+3 (r0 = 4*rg),
    // sliding register window over zero-padded K — no predication.
    float4 Kb = Kp4[32 + rg];       // K[d..d+3],   d = r0
    float4 Ka = Kp4[31 + rg];       // K[d-4..d-1]
    #pragma unroll 4
    for (int it = 0; it < 32; it++) {
        float4 ua = uA4[it], ub = uB4[it];
        float k0 = Kb.x, k1 = Kb.y, k2 = Kb.z, k3 = Kb.w;   // off 0..3
        float km1 = Ka.w, km2 = Ka.z, km3 = Ka.y;           // off -1..-3
        accA[0] += k0 * ua.x + km1 * ua.y + km2 * ua.z + km3 * ua.w;
        accA[1] += k1 * ua.x + k0  * ua.y + km1 * ua.z + km2 * ua.w;
        accA[2] += k2 * ua.x + k1  * ua.y + k0  * ua.z + km1 * ua.w;
        accA[3] += k3 * ua.x + k2  * ua.y + k1  * ua.z + k0  * ua.w;
        accB[0] += k0 * ub.x + km1 * ub.y + km2 * ub.z + km3 * ub.w;
        accB[1] += k1 * ub.x + k0  * ub.y + km1 * ub.z + km2 * ub.w;
        accB[2] += k2 * ub.x + k1  * ub.y + k0  * ub.z + km1 * ub.w;
        accB[3] += k3 * ub.x + k2  * ub.y + k1  * ub.z + k0  * ub.w;
        Kb = Ka;
        if (it < 31) Ka = Kp4[30 + rg - it];
    }

    // y += P[r] . x_c   (Pt[k][r], float4 over r)
    const float4* X4A = (const float4*)(X_s + bA * 64);
    const float4* X4B = (const float4*)(X_s + bB * 64);
    #pragma unroll 4
    for (int kq = 0; kq < 16; kq++) {
        float4 xa = X4A[kq], xb = X4B[kq];
        float4 p0 = *(const float4*)(Pt_s + (4 * kq + 0) * 128 + 4 * rg);
        float4 p1 = *(const float4*)(Pt_s + (4 * kq + 1) * 128 + 4 * rg);
        float4 p2 = *(const float4*)(Pt_s + (4 * kq + 2) * 128 + 4 * rg);
        float4 p3 = *(const float4*)(Pt_s + (4 * kq + 3) * 128 + 4 * rg);
        accA[0] += p0.x * xa.x + p1.x * xa.y + p2.x * xa.z + p3.x * xa.w;
        accA[1] += p0.y * xa.x + p1.y * xa.y + p2.y * xa.z + p3.y * xa.w;
        accA[2] += p0.z * xa.x + p1.z * xa.y + p2.z * xa.z + p3.z * xa.w;
        accA[3] += p0.w * xa.x + p1.w * xa.y + p2.w * xa.z + p3.w * xa.w;
        accB[0] += p0.x * xb.x + p1.x * xb.y + p2.x * xb.z + p3.x * xb.w;
        accB[1] += p0.y * xb.x + p1.y * xb.y + p2.y * xb.z + p3.y * xb.w;
        accB[2] += p0.z * xb.x + p1.z * xb.y + p2.z * xb.z + p3.z * xb.w;
        accB[3] += p0.w * xb.x + p1.w * xb.y + p2.w * xb.z + p3.w * xb.w;
    }

    // + D * u  and store
    {
        float4 ua = uA4[rg], ub = uB4[rg];
        accA[0] += Dv * ua.x; accA[1] += Dv * ua.y;
        accA[2] += Dv * ua.z; accA[3] += Dv * ua.w;
        accB[0] += Dv * ub.x; accB[1] += Dv * ub.y;
        accB[2] += Dv * ub.z; accB[3] += Dv * ub.w;
    }
    float* yA = y + (size_t)(bt * 16 + bA) * SEQLEN + (size_t)c * TCHUNK + 4 * rg;
    float* yB = y + (size_t)(bt * 16 + bB) * SEQLEN + (size_t)c * TCHUNK + 4 * rg;
    *(float4*)yA = make_float4(accA[0], accA[1], accA[2], accA[3]);
    *(float4*)yB = make_float4(accB[0], accB[1], accB[2], accB[3]);
}

// ---------------- launch ----------------
extern "C" void kernel_launch(void* const* d_in, const int* in_sizes, int n_in,
                              void* d_out, int out_size)
{
    const float* u  = (const float*)d_in[0];
    const float* A  = (const float*)d_in[1];
    const float* Bv = (const float*)d_in[2];
    const float* Cv = (const float*)d_in[3];
    const float* Dp = (const float*)d_in[4];
    const float* ls = (const float*)d_in[5];
    float* y = (float*)d_out;

    static const int SMEM_SETUP = 12736 * 4;  // 50944 B
    cudaFuncSetAttribute(ssm_setup, cudaFuncAttributeMaxDynamicSharedMemorySize,
                         SMEM_SETUP);

    ssm_setup<<<1, 256, SMEM_SETUP>>>(A, Bv, Cv, ls);
    ssm_gproj<<<dim3(NCHUNK, NBATCH / 16), 256>>>(u);
    ssm_scan<<<NBATCH, 64>>>();
    ssm_out<<<dim3(NCHUNK, NBATCH / 16), 256>>>(u, y, Dp);
}